// round 4
// baseline (speedup 1.0000x reference)
#include <cuda_runtime.h>
#include <cstdint>

// Problem constants
#define B        64
#define N_SV     63
#define HID      512
#define NEW_W    28
#define NEW_H    28
#define NCELL    (NEW_W * NEW_H)     // 784
#define HT       8                   // h-channels per block
#define NTHREADS 256
#define TILE_F   (HT * NCELL)        // 6272 floats per block tile
#define TILE_F4  (TILE_F / 4)        // 1568 float4

// ---------------------------------------------------------------------------
// Single fused kernel, no smem grid tile:
//   Each block exclusively owns output tile (b, h0..h0+8, all 784 cells).
//   Phase A: store zeros for the whole tile DIRECTLY to global (STG.128,
//            fully coalesced) — no shared-memory round trip.
//   sync    : intra-CTA ordering of zeros vs. patches.
//   Phase B: <=504 (agent, channel) pairs issue no-return global atomicMax
//            (REDG.MAX) to patch the occupied cells. Values <= 0 skipped
//            (cannot beat the 0 init); all survivors >= 0, so int-compare
//            on float bits is exact.
// ---------------------------------------------------------------------------
__global__ __launch_bounds__(NTHREADS)
void fused_raster_kernel(const float* __restrict__ pos,     // (B, N_SV, 3)
                         const float* __restrict__ enc,     // (B, N_SV, HID)
                         const int*   __restrict__ lengths, // (B,)
                         float* __restrict__ out)           // (B, HID, 28, 28)
{
    const int b   = blockIdx.x;
    const int h0  = blockIdx.y * HT;
    const int tid = threadIdx.x;

    __shared__ int sCell[N_SV];   // cell index per agent, -1 if invalid

    // --- Stage 0: agent validity + cell index (first 63 threads) ---
    if (tid < N_SV) {
        int cell = -1;
        if (tid < lengths[b]) {
            const float x = pos[(b * N_SV + tid) * 3 + 0];
            const float y = pos[(b * N_SV + tid) * 3 + 1];
            int xI = (int)(x * 0.125f);   // 28/224 = 1/8 exact; trunc toward 0
            int yI = (int)(y * 0.125f);
            if (xI < NEW_W && yI < NEW_H) {
                if (xI < 0) xI = 0;
                if (yI < 0) yI = 0;
                cell = xI * NEW_H + yI;
            }
        }
        sCell[tid] = cell;
    }

    // --- Phase A: zero the tile directly in global memory ---
    float* outB = out + ((size_t)b * HID + h0) * NCELL;
    float4* outB4 = (float4*)outB;
    const float4 z = make_float4(0.f, 0.f, 0.f, 0.f);
    #pragma unroll
    for (int k = 0; k < (TILE_F4 + NTHREADS - 1) / NTHREADS; k++) {
        int j = tid + k * NTHREADS;
        if (j < TILE_F4) outB4[j] = z;
    }

    // Order: sCell writes visible + zeros complete before patches.
    __syncthreads();

    // --- Phase B: patch occupied cells with REDG.MAX ---
    // 63 agents x 8 channels = 504 (a, hh) pairs; 2 iterations per thread.
    const float* encB = enc + (size_t)b * N_SV * HID + h0;
    int* outBi = (int*)outB;
    for (int i = tid; i < N_SV * HT; i += NTHREADS) {
        const int a    = i >> 3;          // i / HT
        const int hh   = i & (HT - 1);    // i % HT
        const int cell = sCell[a];
        if (cell >= 0) {
            const float v = encB[a * HID + hh];   // coalesced 8-float rows
            if (v > 0.f)
                atomicMax(outBi + hh * NCELL + cell, __float_as_int(v));
        }
    }
}

extern "C" void kernel_launch(void* const* d_in, const int* in_sizes, int n_in,
                              void* d_out, int out_size) {
    const float* pos     = (const float*)d_in[0];   // (B, N_SV, 3)
    const float* enc     = (const float*)d_in[1];   // (B, N_SV, HID)
    const int*   lengths = (const int*)d_in[2];     // (B,)

    dim3 grid(B, HID / HT);            // (64, 64) = 4096 blocks
    fused_raster_kernel<<<grid, NTHREADS>>>(pos, enc, lengths, (float*)d_out);
}